// round 15
// baseline (speedup 1.0000x reference)
#include <cuda_runtime.h>
#include <cuda_fp16.h>
#include <math_constants.h>

typedef unsigned long long u64;
typedef unsigned int u32;

constexpr int cB=4, cT=8192, cD=512, cNB=512, cDH=64;
constexpr size_t QKV_SZ = (size_t)cB*16*8*cNB*cDH;   // 16,777,216 per tensor

__device__ __half g_qkvh[3*QKV_SZ];
__device__ __half g_xh[(size_t)32768*512];
__device__ __half g_wh[(size_t)1536*512];

// ------------------------- helpers -------------------------
__device__ __forceinline__ u32 smem_u32(const void* p){u32 a;asm("{ .reg .u64 t; cvta.to.shared.u64 t,%1; cvt.u32.u64 %0,t; }":"=r"(a):"l"(p));return a;}
__device__ __forceinline__ void ldsm4(u32* r, u32 addr){
  asm volatile("ldmatrix.sync.aligned.m8n8.x4.shared.b16 {%0,%1,%2,%3},[%4];"
    : "=r"(r[0]),"=r"(r[1]),"=r"(r[2]),"=r"(r[3]) : "r"(addr));
}
__device__ __forceinline__ void ldsm4t(u32* r, u32 addr){
  asm volatile("ldmatrix.sync.aligned.m8n8.x4.trans.shared.b16 {%0,%1,%2,%3},[%4];"
    : "=r"(r[0]),"=r"(r[1]),"=r"(r[2]),"=r"(r[3]) : "r"(addr));
}
__device__ __forceinline__ void mmah(float* c, const u32* a, u32 b0, u32 b1){
  asm volatile("mma.sync.aligned.m16n8k16.row.col.f32.f16.f16.f32 "
    "{%0,%1,%2,%3},{%4,%5,%6,%7},{%8,%9},{%0,%1,%2,%3};"
    : "+f"(c[0]),"+f"(c[1]),"+f"(c[2]),"+f"(c[3])
    : "r"(a[0]),"r"(a[1]),"r"(a[2]),"r"(a[3]),"r"(b0),"r"(b1));
}
__device__ __forceinline__ u32 pack_h2(float x,float y){
  __half2 h=__floats2half2_rn(x,y); return *(u32*)&h;
}
__device__ __forceinline__ void cpa16(u32 dst, const void* src){
  asm volatile("cp.async.cg.shared.global [%0],[%1],16;"::"r"(dst),"l"(src));
}
__device__ __forceinline__ void cpa_commit(){asm volatile("cp.async.commit_group;");}
__device__ __forceinline__ void cpa_wait1(){asm volatile("cp.async.wait_group 1;");}

// ------------------------- merged split kernel -------------------------
__global__ void __launch_bounds__(256) splitall(const float* __restrict__ x,
    const float* __restrict__ Wq,const float* __restrict__ Wk,const float* __restrict__ Wv){
  int bb=blockIdx.x;
  if(bb<16384){
    size_t i=(size_t)bb*256+threadIdx.x;
    float4 v=((const float4*)x)[i];
    __half2* ph=(__half2*)(g_xh+i*4);
    ph[0]=__floats2half2_rn(v.x,v.y);
    ph[1]=__floats2half2_rn(v.z,v.w);
  } else {
    size_t i=(size_t)(bb-16384)*256+threadIdx.x;
    int p=(int)(i>>16);
    const float* W=(p==0)?Wq:(p==1)?Wk:Wv;
    float4 v=((const float4*)W)[i&65535];
    __half2* ph=(__half2*)(g_wh+i*4);
    ph[0]=__floats2half2_rn(v.x,v.y);
    ph[1]=__floats2half2_rn(v.z,v.w);
  }
}

// ------------------------- HMMA fused QKV GEMM (fp16, 1-product) -----------
constexpr float SCALE2 = 0.044194173824159216f * 1.4426950408889634f;
constexpr int QST = 36864;   // bytes per stage (2 arrays x 128*144B)

__global__ void __launch_bounds__(256,2)
qkv_mma(const float* __restrict__ bq,const float* __restrict__ bk,const float* __restrict__ bv){
  extern __shared__ __half qsm[];
  const int tid=threadIdx.x, warp=tid>>5, lane=tid&31;
  const int wm=warp>>1, wn=warp&1;
  const int bn=blockIdx.x, bm=blockIdx.y;
  const size_t m0=(size_t)bm*128, j0=(size_t)bn*128;
  const u32 smb=smem_u32(qsm);

  float acc[2][8][4];
#pragma unroll
  for(int a=0;a<2;++a)
#pragma unroll
    for(int b=0;b<8;++b)
#pragma unroll
      for(int c=0;c<4;++c) acc[a][b][c]=0.f;

  const int cr=tid>>3, cc=tid&7;
  const u32 dsl=(u32)(cr*144+cc*16);

  const u32 oA=(u32)((wm*32+(lane&15))*144)+(lane>>4)*16;
  const u32 oB=18432+(u32)((wn*64+(lane&7)+((lane>>3)&1)*8)*144)+(lane>>4)*16;

#pragma unroll
  for(int st=0;st<2;++st){
    u32 d=smb+st*QST;
    size_t o=(size_t)st*64;
#pragma unroll
    for(int i=0;i<4;++i){
      u32 ds=dsl+(u32)(i*32*144);
      size_t gr=(size_t)(cr+i*32);
      cpa16(d+ds,       g_xh+(m0+gr)*512+cc*8+o);
      cpa16(d+18432+ds, g_wh+(j0+gr)*512+cc*8+o);
    }
    cpa_commit();
  }

  int cur=0, nxt=2;
#pragma unroll 1
  for(int kc=0;kc<8;++kc){
    cpa_wait1();
    __syncthreads();
    if(kc<6){
      u32 d=smb+nxt*QST;
      size_t o=(size_t)(kc+2)*64;
#pragma unroll
      for(int i=0;i<4;++i){
        u32 ds=dsl+(u32)(i*32*144);
        size_t gr=(size_t)(cr+i*32);
        cpa16(d+ds,       g_xh+(m0+gr)*512+cc*8+o);
        cpa16(d+18432+ds, g_wh+(j0+gr)*512+cc*8+o);
      }
    }
    cpa_commit();
    const u32 so=smb+cur*QST;
    const u32 aA=so+oA, aB=so+oB;
#pragma unroll
    for(int ks=0;ks<4;++ks){
      const u32 kb=(u32)(ks*32);
      u32 a0[4],a1[4];
      ldsm4(a0,aA+kb); ldsm4(a1,aA+kb+16*144);
#pragma unroll
      for(int j=0;j<4;++j){
        u32 bj[4];
        ldsm4(bj,aB+(u32)(j*16*144)+kb);
        mmah(acc[0][2*j],  a0,bj[0],bj[2]); mmah(acc[0][2*j+1],a0,bj[1],bj[3]);
        mmah(acc[1][2*j],  a1,bj[0],bj[2]); mmah(acc[1][2*j+1],a1,bj[1],bj[3]);
      }
    }
    cur=(cur==2)?0:cur+1;
    nxt=(nxt==2)?0:nxt+1;
  }

  const int which=bn>>2;
  const float* bias=(which==0)?bq:(which==1)?bk:bv;
  const float qs=(which==0)?SCALE2:1.0f;
  const int jlb=(bn&3)*128+wn*64;
  const int h=jlb>>6;
  const int g=lane>>2, t4=lane&3;
  __half* baseh=g_qkvh+(size_t)which*QKV_SZ;
#pragma unroll
  for(int mt=0;mt<2;++mt){
#pragma unroll
    for(int rr=0;rr<2;++rr){
      int mg=bm*128+wm*32+mt*16+rr*8+g;
      int b_=mg>>13, n_=(mg&8191)>>4, s_=mg&15;
      size_t off=((size_t)((b_*16+s_)*8+h))*32768 + (size_t)n_*64 + t4*2;
#pragma unroll
      for(int nt=0;nt<8;++nt){
        float2 bb=*(const float2*)(bias+jlb+nt*8+t4*2);
        float ox=(acc[mt][nt][rr*2]  +bb.x)*qs;
        float oy=(acc[mt][nt][rr*2+1]+bb.y)*qs;
        *(u32*)(baseh+off+nt*8)=pack_h2(ox,oy);
      }
    }
  }
}

// ------------------------- HMMA flash attention (fp16, m32n64 warp tile) ---
// Block = (qt, bsh), 128 threads (4 warps), warp owns 32 q-rows. 3 CTA/SM
// (occupancy raised from 2: smem 3x73728=221184 <= 227KB, 128 regs).
__global__ void __launch_bounds__(128,3)
attn_mma(float* __restrict__ out){
  extern __shared__ __half sm[];
  const int tid=threadIdx.x, warp=tid>>5, lane=tid&31;
  const int g=lane>>2, t4=lane&3;
  const int qt=blockIdx.x, bsh=blockIdx.y;
  const int h=bsh&7, s=(bsh>>3)&15, b_=bsh>>7;
  const size_t hoff=(size_t)bsh*32768;
  const __half *Qh=g_qkvh+hoff;
  const __half *Kh=g_qkvh+QKV_SZ+hoff, *Vh=g_qkvh+2*QKV_SZ+hoff;
  const u32 smb=smem_u32(sm);
  const u32 kvb=smb+18432;

  const int kr=tid>>3, kc8=tid&7;
  const u32 kdl=(u32)(kr*144+kc8*16);
  const size_t kgl=(size_t)kr*64+kc8*8;

  // prologue: Q tile (8 slots/thread) + KV stage0 ; then KV stage1
#pragma unroll
  for(int i=0;i<8;++i){
    int idx=tid+i*128, r=idx>>3, c8=idx&7;
    cpa16(smb+(u32)(r*144+c8*16), Qh+(size_t)(qt*128+r)*64+c8*8);
  }
#pragma unroll
  for(int i=0;i<4;++i){
    u32 ds=kdl+(u32)(i*16*144);
    size_t gs=kgl+(size_t)i*16*64;
    cpa16(kvb+ds,      Kh+gs);
    cpa16(kvb+9216+ds, Vh+gs);
  }
  cpa_commit();
  {
    u32 d=kvb+18432;
#pragma unroll
    for(int i=0;i<4;++i){
      u32 ds=kdl+(u32)(i*16*144);
      size_t gs=kgl+(size_t)i*16*64+64*64;
      cpa16(d+ds,      Kh+gs);
      cpa16(d+9216+ds, Vh+gs);
    }
    cpa_commit();
  }

  float accO[2][8][4];
#pragma unroll
  for(int a=0;a<2;++a)
#pragma unroll
    for(int nt=0;nt<8;++nt)
#pragma unroll
      for(int c=0;c<4;++c) accO[a][nt][c]=0.f;
  float l0[2]={0.f,0.f}, l1[2]={0.f,0.f};

  const u32 aQh=smb+(u32)((warp*32+(lane&15))*144)+(lane>>4)*16;
  const u32 kvr=(u32)(((lane&7)+((lane>>3)&1)*8)*144)+(lane>>4)*16;

  u32 qf[2][4][4];   // Q fragments resident (2 m16-halves x 4 ks)

  int cur=0, nxt=2;
#pragma unroll 1
  for(int it=0;it<8;++it){
    cpa_wait1();
    __syncthreads();
    if(it==0){
#pragma unroll
      for(int a=0;a<2;++a)
#pragma unroll
        for(int ks=0;ks<4;++ks)
          ldsm4(qf[a][ks], aQh+(u32)(a*16*144+ks*32));
    }
    if(it<6){
      const size_t mo=(size_t)(it+2)*64*64;
      u32 d=kvb+nxt*18432;
#pragma unroll
      for(int i=0;i<4;++i){
        u32 ds=kdl+(u32)(i*16*144);
        size_t gs=kgl+(size_t)i*16*64+mo;
        cpa16(d+ds,      Kh+gs);
        cpa16(d+9216+ds, Vh+gs);
      }
    }
    cpa_commit();
    const u32 aK=kvb+cur*18432+kvr;
    const u32 aV=aK+9216;

    // S = Qh·K^T, warp tile m32 x n64
    float accS[2][8][4];
#pragma unroll
    for(int a=0;a<2;++a)
#pragma unroll
      for(int nt=0;nt<8;++nt)
#pragma unroll
        for(int c=0;c<4;++c) accS[a][nt][c]=0.f;
#pragma unroll
    for(int ks=0;ks<4;++ks){
      u32 kb=(u32)(ks*32);
#pragma unroll
      for(int j=0;j<4;++j){
        u32 bh[4];
        ldsm4(bh,aK+(u32)(j*16*144)+kb);
        mmah(accS[0][2*j],qf[0][ks],bh[0],bh[2]); mmah(accS[0][2*j+1],qf[0][ks],bh[1],bh[3]);
        mmah(accS[1][2*j],qf[1][ks],bh[0],bh[2]); mmah(accS[1][2*j+1],qf[1][ks],bh[1],bh[3]);
      }
    }

    // fused exp2 + pack + PV per ks-group
#pragma unroll
    for(int ks=0;ks<4;++ks){
      u32 ah[2][4];
#pragma unroll
      for(int a=0;a<2;++a){
        float e0=exp2f(accS[a][2*ks][0]),   e1=exp2f(accS[a][2*ks][1]);
        float e2=exp2f(accS[a][2*ks][2]),   e3=exp2f(accS[a][2*ks][3]);
        float f0=exp2f(accS[a][2*ks+1][0]), f1=exp2f(accS[a][2*ks+1][1]);
        float f2=exp2f(accS[a][2*ks+1][2]), f3=exp2f(accS[a][2*ks+1][3]);
        l0[a]+=e0+e1+f0+f1;
        l1[a]+=e2+e3+f2+f3;
        ah[a][0]=pack_h2(e0,e1); ah[a][1]=pack_h2(e2,e3);
        ah[a][2]=pack_h2(f0,f1); ah[a][3]=pack_h2(f2,f3);
      }
      u32 kb=(u32)(ks*16*144);
#pragma unroll
      for(int j=0;j<4;++j){
        u32 bh[4];
        ldsm4t(bh,aV+kb+(u32)(j*32));
        mmah(accO[0][2*j],ah[0],bh[0],bh[1]); mmah(accO[0][2*j+1],ah[0],bh[2],bh[3]);
        mmah(accO[1][2*j],ah[1],bh[0],bh[1]); mmah(accO[1][2*j+1],ah[1],bh[2],bh[3]);
      }
    }
    cur=(cur==2)?0:cur+1;
    nxt=(nxt==2)?0:nxt+1;
  }

  // final l reduction + normalize + store (per m16 half)
#pragma unroll
  for(int a=0;a<2;++a){
    float L0=l0[a], L1=l1[a];
    L0+=__shfl_xor_sync(0xffffffffu,L0,1); L0+=__shfl_xor_sync(0xffffffffu,L0,2);
    L1+=__shfl_xor_sync(0xffffffffu,L1,1); L1+=__shfl_xor_sync(0xffffffffu,L1,2);
    float iv0=1.f/L0, iv1=1.f/L1;
    int r0=qt*128+warp*32+a*16+g;
    int t0=r0*16+s, t1=(r0+8)*16+s;
    float* o0=out+((size_t)(b_*cT+t0))*cD + h*64 + t4*2;
    float* o1=out+((size_t)(b_*cT+t1))*cD + h*64 + t4*2;
#pragma unroll
    for(int nt=0;nt<8;++nt){
      *(float2*)(o0+nt*8)=make_float2(accO[a][nt][0]*iv0,accO[a][nt][1]*iv0);
      *(float2*)(o1+nt*8)=make_float2(accO[a][nt][2]*iv1,accO[a][nt][3]*iv1);
    }
  }
}

// ------------------------- launch -------------------------
extern "C" void kernel_launch(void* const* d_in, const int* in_sizes, int n_in,
                              void* d_out, int out_size){
  const float* x =(const float*)d_in[0];
  const float* Wq=(const float*)d_in[1];
  const float* bq=(const float*)d_in[2];
  const float* Wk=(const float*)d_in[3];
  const float* bk=(const float*)d_in[4];
  const float* Wv=(const float*)d_in[5];
  const float* bv=(const float*)d_in[6];
  float* out=(float*)d_out;

  cudaFuncSetAttribute(qkv_mma, cudaFuncAttributeMaxDynamicSharedMemorySize, 3*QST);
  cudaFuncSetAttribute(attn_mma, cudaFuncAttributeMaxDynamicSharedMemorySize, 73728);

  splitall<<<17152,256>>>(x,Wq,Wk,Wv);
  qkv_mma<<<dim3(12,256),256,3*QST>>>(bq,bk,bv);
  attn_mma<<<dim3(4,512),128,73728>>>(out);
}

// round 16
// speedup vs baseline: 1.0482x; 1.0482x over previous
#include <cuda_runtime.h>
#include <cuda_fp16.h>
#include <math_constants.h>

typedef unsigned long long u64;
typedef unsigned int u32;

constexpr int cB=4, cT=8192, cD=512, cNB=512, cDH=64;
constexpr size_t QKV_SZ = (size_t)cB*16*8*cNB*cDH;   // 16,777,216 per tensor

__device__ __half g_qkvh[3*QKV_SZ];
__device__ __half g_xh[(size_t)32768*512];
__device__ __half g_wh[(size_t)1536*512];

// ------------------------- helpers -------------------------
__device__ __forceinline__ u32 smem_u32(const void* p){u32 a;asm("{ .reg .u64 t; cvta.to.shared.u64 t,%1; cvt.u32.u64 %0,t; }":"=r"(a):"l"(p));return a;}
__device__ __forceinline__ void ldsm4(u32* r, u32 addr){
  asm volatile("ldmatrix.sync.aligned.m8n8.x4.shared.b16 {%0,%1,%2,%3},[%4];"
    : "=r"(r[0]),"=r"(r[1]),"=r"(r[2]),"=r"(r[3]) : "r"(addr));
}
__device__ __forceinline__ void ldsm4t(u32* r, u32 addr){
  asm volatile("ldmatrix.sync.aligned.m8n8.x4.trans.shared.b16 {%0,%1,%2,%3},[%4];"
    : "=r"(r[0]),"=r"(r[1]),"=r"(r[2]),"=r"(r[3]) : "r"(addr));
}
__device__ __forceinline__ void mmah(float* c, const u32* a, u32 b0, u32 b1){
  asm volatile("mma.sync.aligned.m16n8k16.row.col.f32.f16.f16.f32 "
    "{%0,%1,%2,%3},{%4,%5,%6,%7},{%8,%9},{%0,%1,%2,%3};"
    : "+f"(c[0]),"+f"(c[1]),"+f"(c[2]),"+f"(c[3])
    : "r"(a[0]),"r"(a[1]),"r"(a[2]),"r"(a[3]),"r"(b0),"r"(b1));
}
__device__ __forceinline__ void mmah16(u32* c, const u32* a, u32 b0, u32 b1){
  asm volatile("mma.sync.aligned.m16n8k16.row.col.f16.f16.f16.f16 "
    "{%0,%1},{%2,%3,%4,%5},{%6,%7},{%0,%1};"
    : "+r"(c[0]),"+r"(c[1])
    : "r"(a[0]),"r"(a[1]),"r"(a[2]),"r"(a[3]),"r"(b0),"r"(b1));
}
__device__ __forceinline__ u32 h2exp2(u32 x){
  u32 y; asm("ex2.approx.f16x2 %0, %1;" : "=r"(y) : "r"(x)); return y;
}
__device__ __forceinline__ u32 pack_h2(float x,float y){
  __half2 h=__floats2half2_rn(x,y); return *(u32*)&h;
}
__device__ __forceinline__ void cpa16(u32 dst, const void* src){
  asm volatile("cp.async.cg.shared.global [%0],[%1],16;"::"r"(dst),"l"(src));
}
__device__ __forceinline__ void cpa_commit(){asm volatile("cp.async.commit_group;");}
__device__ __forceinline__ void cpa_wait1(){asm volatile("cp.async.wait_group 1;");}

// ------------------------- merged split kernel -------------------------
__global__ void __launch_bounds__(256) splitall(const float* __restrict__ x,
    const float* __restrict__ Wq,const float* __restrict__ Wk,const float* __restrict__ Wv){
  int bb=blockIdx.x;
  if(bb<16384){
    size_t i=(size_t)bb*256+threadIdx.x;
    float4 v=((const float4*)x)[i];
    __half2* ph=(__half2*)(g_xh+i*4);
    ph[0]=__floats2half2_rn(v.x,v.y);
    ph[1]=__floats2half2_rn(v.z,v.w);
  } else {
    size_t i=(size_t)(bb-16384)*256+threadIdx.x;
    int p=(int)(i>>16);
    const float* W=(p==0)?Wq:(p==1)?Wk:Wv;
    float4 v=((const float4*)W)[i&65535];
    __half2* ph=(__half2*)(g_wh+i*4);
    ph[0]=__floats2half2_rn(v.x,v.y);
    ph[1]=__floats2half2_rn(v.z,v.w);
  }
}

// ------------------------- HMMA fused QKV GEMM (fp16, 1-product) -----------
constexpr float SCALE2 = 0.044194173824159216f * 1.4426950408889634f;
constexpr int QST = 36864;   // bytes per stage (2 arrays x 128*144B)

__global__ void __launch_bounds__(256,2)
qkv_mma(const float* __restrict__ bq,const float* __restrict__ bk,const float* __restrict__ bv){
  extern __shared__ __half qsm[];
  const int tid=threadIdx.x, warp=tid>>5, lane=tid&31;
  const int wm=warp>>1, wn=warp&1;
  const int bn=blockIdx.x, bm=blockIdx.y;
  const size_t m0=(size_t)bm*128, j0=(size_t)bn*128;
  const u32 smb=smem_u32(qsm);

  float acc[2][8][4];
#pragma unroll
  for(int a=0;a<2;++a)
#pragma unroll
    for(int b=0;b<8;++b)
#pragma unroll
      for(int c=0;c<4;++c) acc[a][b][c]=0.f;

  const int cr=tid>>3, cc=tid&7;
  const u32 dsl=(u32)(cr*144+cc*16);

  const u32 oA=(u32)((wm*32+(lane&15))*144)+(lane>>4)*16;
  const u32 oB=18432+(u32)((wn*64+(lane&7)+((lane>>3)&1)*8)*144)+(lane>>4)*16;

#pragma unroll
  for(int st=0;st<2;++st){
    u32 d=smb+st*QST;
    size_t o=(size_t)st*64;
#pragma unroll
    for(int i=0;i<4;++i){
      u32 ds=dsl+(u32)(i*32*144);
      size_t gr=(size_t)(cr+i*32);
      cpa16(d+ds,       g_xh+(m0+gr)*512+cc*8+o);
      cpa16(d+18432+ds, g_wh+(j0+gr)*512+cc*8+o);
    }
    cpa_commit();
  }

  int cur=0, nxt=2;
#pragma unroll 1
  for(int kc=0;kc<8;++kc){
    cpa_wait1();
    __syncthreads();
    if(kc<6){
      u32 d=smb+nxt*QST;
      size_t o=(size_t)(kc+2)*64;
#pragma unroll
      for(int i=0;i<4;++i){
        u32 ds=dsl+(u32)(i*32*144);
        size_t gr=(size_t)(cr+i*32);
        cpa16(d+ds,       g_xh+(m0+gr)*512+cc*8+o);
        cpa16(d+18432+ds, g_wh+(j0+gr)*512+cc*8+o);
      }
    }
    cpa_commit();
    const u32 so=smb+cur*QST;
    const u32 aA=so+oA, aB=so+oB;
#pragma unroll
    for(int ks=0;ks<4;++ks){
      const u32 kb=(u32)(ks*32);
      u32 a0[4],a1[4];
      ldsm4(a0,aA+kb); ldsm4(a1,aA+kb+16*144);
#pragma unroll
      for(int j=0;j<4;++j){
        u32 bj[4];
        ldsm4(bj,aB+(u32)(j*16*144)+kb);
        mmah(acc[0][2*j],  a0,bj[0],bj[2]); mmah(acc[0][2*j+1],a0,bj[1],bj[3]);
        mmah(acc[1][2*j],  a1,bj[0],bj[2]); mmah(acc[1][2*j+1],a1,bj[1],bj[3]);
      }
    }
    cur=(cur==2)?0:cur+1;
    nxt=(nxt==2)?0:nxt+1;
  }

  const int which=bn>>2;
  const float* bias=(which==0)?bq:(which==1)?bk:bv;
  const float qs=(which==0)?SCALE2:1.0f;
  const int jlb=(bn&3)*128+wn*64;
  const int h=jlb>>6;
  const int g=lane>>2, t4=lane&3;
  __half* baseh=g_qkvh+(size_t)which*QKV_SZ;
#pragma unroll
  for(int mt=0;mt<2;++mt){
#pragma unroll
    for(int rr=0;rr<2;++rr){
      int mg=bm*128+wm*32+mt*16+rr*8+g;
      int b_=mg>>13, n_=(mg&8191)>>4, s_=mg&15;
      size_t off=((size_t)((b_*16+s_)*8+h))*32768 + (size_t)n_*64 + t4*2;
#pragma unroll
      for(int nt=0;nt<8;++nt){
        float2 bb=*(const float2*)(bias+jlb+nt*8+t4*2);
        float ox=(acc[mt][nt][rr*2]  +bb.x)*qs;
        float oy=(acc[mt][nt][rr*2+1]+bb.y)*qs;
        *(u32*)(baseh+off+nt*8)=pack_h2(ox,oy);
      }
    }
  }
}

// ------------------------- HMMA flash attention ---------------------------
// Block = (qt, bsh), 128 threads (4 warps), warp m32n64, 2 CTA/SM.
// S-GEMM in fp16-accumulate (2x MMA rate); the fp16 S fragment is directly
// the packed PV A-fragment, so P = ex2.approx.f16x2(S) with no packing.
// PV stays fp32-acc. l sums via hadd2 + cvt. 3-stage K/V cp.async ring.
__global__ void __launch_bounds__(128,2)
attn_mma(float* __restrict__ out){
  extern __shared__ __half sm[];
  const int tid=threadIdx.x, warp=tid>>5, lane=tid&31;
  const int g=lane>>2, t4=lane&3;
  const int qt=blockIdx.x, bsh=blockIdx.y;
  const int h=bsh&7, s=(bsh>>3)&15, b_=bsh>>7;
  const size_t hoff=(size_t)bsh*32768;
  const __half *Qh=g_qkvh+hoff;
  const __half *Kh=g_qkvh+QKV_SZ+hoff, *Vh=g_qkvh+2*QKV_SZ+hoff;
  const u32 smb=smem_u32(sm);
  const u32 kvb=smb+18432;

  const int kr=tid>>3, kc8=tid&7;
  const u32 kdl=(u32)(kr*144+kc8*16);
  const size_t kgl=(size_t)kr*64+kc8*8;

  // prologue: Q tile + KV stage0 ; then KV stage1
#pragma unroll
  for(int i=0;i<8;++i){
    int idx=tid+i*128, r=idx>>3, c8=idx&7;
    cpa16(smb+(u32)(r*144+c8*16), Qh+(size_t)(qt*128+r)*64+c8*8);
  }
#pragma unroll
  for(int i=0;i<4;++i){
    u32 ds=kdl+(u32)(i*16*144);
    size_t gs=kgl+(size_t)i*16*64;
    cpa16(kvb+ds,      Kh+gs);
    cpa16(kvb+9216+ds, Vh+gs);
  }
  cpa_commit();
  {
    u32 d=kvb+18432;
#pragma unroll
    for(int i=0;i<4;++i){
      u32 ds=kdl+(u32)(i*16*144);
      size_t gs=kgl+(size_t)i*16*64+64*64;
      cpa16(d+ds,      Kh+gs);
      cpa16(d+9216+ds, Vh+gs);
    }
    cpa_commit();
  }

  float accO[2][8][4];
#pragma unroll
  for(int a=0;a<2;++a)
#pragma unroll
    for(int nt=0;nt<8;++nt)
#pragma unroll
      for(int c=0;c<4;++c) accO[a][nt][c]=0.f;
  float l0[2]={0.f,0.f}, l1[2]={0.f,0.f};

  const u32 aQh=smb+(u32)((warp*32+(lane&15))*144)+(lane>>4)*16;
  const u32 kvr=(u32)(((lane&7)+((lane>>3)&1)*8)*144)+(lane>>4)*16;

  u32 qf[2][4][4];   // Q fragments resident (2 m16-halves x 4 ks)

  int cur=0, nxt=2;
#pragma unroll 1
  for(int it=0;it<8;++it){
    cpa_wait1();
    __syncthreads();
    if(it==0){
#pragma unroll
      for(int a=0;a<2;++a)
#pragma unroll
        for(int ks=0;ks<4;++ks)
          ldsm4(qf[a][ks], aQh+(u32)(a*16*144+ks*32));
    }
    if(it<6){
      const size_t mo=(size_t)(it+2)*64*64;
      u32 d=kvb+nxt*18432;
#pragma unroll
      for(int i=0;i<4;++i){
        u32 ds=kdl+(u32)(i*16*144);
        size_t gs=kgl+(size_t)i*16*64+mo;
        cpa16(d+ds,      Kh+gs);
        cpa16(d+9216+ds, Vh+gs);
      }
    }
    cpa_commit();
    const u32 aK=kvb+cur*18432+kvr;
    const u32 aV=aK+9216;

    // S = Qh·K^T in fp16 accumulate; accS[a][nt] = {row g half2, row g+8 half2}
    u32 accS[2][8][2];
#pragma unroll
    for(int a=0;a<2;++a)
#pragma unroll
      for(int nt=0;nt<8;++nt){accS[a][nt][0]=0u; accS[a][nt][1]=0u;}
#pragma unroll
    for(int ks=0;ks<4;++ks){
      u32 kb=(u32)(ks*32);
#pragma unroll
      for(int j=0;j<4;++j){
        u32 bh[4];
        ldsm4(bh,aK+(u32)(j*16*144)+kb);
        mmah16(accS[0][2*j],qf[0][ks],bh[0],bh[2]); mmah16(accS[0][2*j+1],qf[0][ks],bh[1],bh[3]);
        mmah16(accS[1][2*j],qf[1][ks],bh[0],bh[2]); mmah16(accS[1][2*j+1],qf[1][ks],bh[1],bh[3]);
      }
    }

    // fused P=exp2(S) (f16x2 MUFU, no packing) + l sums + PV per ks-group
#pragma unroll
    for(int ks=0;ks<4;++ks){
      u32 ah[2][4];
#pragma unroll
      for(int a=0;a<2;++a){
        ah[a][0]=h2exp2(accS[a][2*ks][0]);   // row g,   k ks*16+2t4..+1
        ah[a][1]=h2exp2(accS[a][2*ks][1]);   // row g+8
        ah[a][2]=h2exp2(accS[a][2*ks+1][0]); // row g,   k ks*16+8+2t4..+1
        ah[a][3]=h2exp2(accS[a][2*ks+1][1]); // row g+8
        __half2 t0=__hadd2(*(__half2*)&ah[a][0], *(__half2*)&ah[a][2]);
        __half2 t1=__hadd2(*(__half2*)&ah[a][1], *(__half2*)&ah[a][3]);
        float2 f0=__half22float2(t0), f1=__half22float2(t1);
        l0[a]+=f0.x+f0.y;
        l1[a]+=f1.x+f1.y;
      }
      u32 kb=(u32)(ks*16*144);
#pragma unroll
      for(int j=0;j<4;++j){
        u32 bh[4];
        ldsm4t(bh,aV+kb+(u32)(j*32));
        mmah(accO[0][2*j],ah[0],bh[0],bh[1]); mmah(accO[0][2*j+1],ah[0],bh[2],bh[3]);
        mmah(accO[1][2*j],ah[1],bh[0],bh[1]); mmah(accO[1][2*j+1],ah[1],bh[2],bh[3]);
      }
    }
    cur=(cur==2)?0:cur+1;
    nxt=(nxt==2)?0:nxt+1;
  }

  // final l reduction + normalize + store (per m16 half)
#pragma unroll
  for(int a=0;a<2;++a){
    float L0=l0[a], L1=l1[a];
    L0+=__shfl_xor_sync(0xffffffffu,L0,1); L0+=__shfl_xor_sync(0xffffffffu,L0,2);
    L1+=__shfl_xor_sync(0xffffffffu,L1,1); L1+=__shfl_xor_sync(0xffffffffu,L1,2);
    float iv0=1.f/L0, iv1=1.f/L1;
    int r0=qt*128+warp*32+a*16+g;
    int t0=r0*16+s, t1=(r0+8)*16+s;
    float* o0=out+((size_t)(b_*cT+t0))*cD + h*64 + t4*2;
    float* o1=out+((size_t)(b_*cT+t1))*cD + h*64 + t4*2;
#pragma unroll
    for(int nt=0;nt<8;++nt){
      *(float2*)(o0+nt*8)=make_float2(accO[a][nt][0]*iv0,accO[a][nt][1]*iv0);
      *(float2*)(o1+nt*8)=make_float2(accO[a][nt][2]*iv1,accO[a][nt][3]*iv1);
    }
  }
}

// ------------------------- launch -------------------------
extern "C" void kernel_launch(void* const* d_in, const int* in_sizes, int n_in,
                              void* d_out, int out_size){
  const float* x =(const float*)d_in[0];
  const float* Wq=(const float*)d_in[1];
  const float* bq=(const float*)d_in[2];
  const float* Wk=(const float*)d_in[3];
  const float* bk=(const float*)d_in[4];
  const float* Wv=(const float*)d_in[5];
  const float* bv=(const float*)d_in[6];
  float* out=(float*)d_out;

  cudaFuncSetAttribute(qkv_mma, cudaFuncAttributeMaxDynamicSharedMemorySize, 3*QST);
  cudaFuncSetAttribute(attn_mma, cudaFuncAttributeMaxDynamicSharedMemorySize, 73728);

  splitall<<<17152,256>>>(x,Wq,Wk,Wv);
  qkv_mma<<<dim3(12,256),256,3*QST>>>(bq,bk,bv);
  attn_mma<<<dim3(4,512),128,73728>>>(out);
}